// round 5
// baseline (speedup 1.0000x reference)
#include <cuda_runtime.h>
#include <cstdint>

// Z gate on qubits (DIM=2): diag[n] = (-1)^popc(n & MASK), MASK bits {13,8,3}.
// Pure signed copy, HBM-bound. x_real,x_imag: [N,B] f32 -> out: [2,N,B] f32.
// N=16384, B=2048. 512 MB total traffic; roofline ~73us @ ~7 TB/s.

static constexpr int N_ROWS   = 16384;
static constexpr int B_COLS   = 2048;
static constexpr uint32_t MASK = (1u << 13) | (1u << 8) | (1u << 3); // 8456
static constexpr int TOTAL4   = N_ROWS * B_COLS / 4; // 8388608 float4 per plane
static constexpr int THREADS  = 256;
static constexpr int UNROLL   = 2;   // float4 per plane per thread

__device__ __forceinline__ float4 flip4(float4 v, uint32_t flip) {
    uint32_t* p = reinterpret_cast<uint32_t*>(&v);
#pragma unroll
    for (int k = 0; k < 4; k++) p[k] ^= flip;
    return v;
}

__global__ void __launch_bounds__(THREADS) z_phase_kernel(
    const float4* __restrict__ xr,
    const float4* __restrict__ xi,
    float4* __restrict__ outr,
    float4* __restrict__ outi)
{
    // Block-tiled: block b owns [b*THREADS*UNROLL, ...), each thread handles
    // indices base+tid and base+tid+THREADS -> both fully coalesced.
    int base = blockIdx.x * (THREADS * UNROLL) + threadIdx.x;

    int idx[UNROLL];
    float4 a[UNROLL], b[UNROLL];
#pragma unroll
    for (int u = 0; u < UNROLL; u++) idx[u] = base + u * THREADS;

    // Front-batch all loads (MLP=4) with evict-first streaming hint.
#pragma unroll
    for (int u = 0; u < UNROLL; u++) a[u] = __ldcs(&xr[idx[u]]);
#pragma unroll
    for (int u = 0; u < UNROLL; u++) b[u] = __ldcs(&xi[idx[u]]);

#pragma unroll
    for (int u = 0; u < UNROLL; u++) {
        // B/4 = 512 float4 per row -> row = idx >> 9
        uint32_t row  = (uint32_t)idx[u] >> 9;
        uint32_t flip = (uint32_t)(__popc(row & MASK) & 1) << 31;
        __stcs(&outr[idx[u]], flip4(a[u], flip));
        __stcs(&outi[idx[u]], flip4(b[u], flip));
    }
}

extern "C" void kernel_launch(void* const* d_in, const int* in_sizes, int n_in,
                              void* d_out, int out_size)
{
    const float4* xr = (const float4*)d_in[0];
    const float4* xi = (const float4*)d_in[1];
    float* out = (float*)d_out;
    float4* outr = (float4*)out;
    float4* outi = (float4*)(out + (size_t)N_ROWS * B_COLS);

    const int blocks = TOTAL4 / (THREADS * UNROLL); // 16384, exact
    z_phase_kernel<<<blocks, THREADS>>>(xr, xi, outr, outi);
}

// round 6
// speedup vs baseline: 1.0051x; 1.0051x over previous
#include <cuda_runtime.h>
#include <cstdint>

// Z gate on qubits (DIM=2): diag[n] = (-1)^popc(n & MASK), MASK bits {13,8,3}
// (INDEX=(0,5,10), L=14, big-endian). Pure signed copy, HBM-bound.
// x_real,x_imag: [N,B] f32 -> out: [2,N,B] f32. N=16384, B=2048.
// 512 MB total traffic. This version uses 256-bit (v8.b32) global ld/st
// (sm_100a-family feature) to halve LSU instruction count per byte.

static constexpr int N_ROWS   = 16384;
static constexpr int B_COLS   = 2048;
static constexpr uint32_t MASK = (1u << 13) | (1u << 8) | (1u << 3); // 8456
static constexpr int TOTAL8   = N_ROWS * B_COLS / 8; // 4194304 f32x8 per plane
static constexpr int THREADS  = 256;

__device__ __forceinline__ void ld_v8(const float* p, uint32_t r[8]) {
    asm volatile(
        "ld.global.v8.b32 {%0,%1,%2,%3,%4,%5,%6,%7}, [%8];"
        : "=r"(r[0]), "=r"(r[1]), "=r"(r[2]), "=r"(r[3]),
          "=r"(r[4]), "=r"(r[5]), "=r"(r[6]), "=r"(r[7])
        : "l"(p));
}

__device__ __forceinline__ void st_v8(float* p, const uint32_t r[8]) {
    asm volatile(
        "st.global.v8.b32 [%0], {%1,%2,%3,%4,%5,%6,%7,%8};"
        :: "l"(p),
           "r"(r[0]), "r"(r[1]), "r"(r[2]), "r"(r[3]),
           "r"(r[4]), "r"(r[5]), "r"(r[6]), "r"(r[7])
        : "memory");
}

__global__ void __launch_bounds__(THREADS) z_phase_kernel(
    const float* __restrict__ xr,
    const float* __restrict__ xi,
    float* __restrict__ outr,
    float* __restrict__ outi)
{
    int i = blockIdx.x * THREADS + threadIdx.x;   // index in units of 8 floats
    // B/8 = 256 f32x8 per row -> row = i >> 8
    uint32_t row  = (uint32_t)i >> 8;
    uint32_t flip = (uint32_t)(__popc(row & MASK) & 1) << 31;

    size_t off = (size_t)i * 8;

    uint32_t a[8], b[8];
    ld_v8(xr + off, a);
    ld_v8(xi + off, b);

#pragma unroll
    for (int k = 0; k < 8; k++) { a[k] ^= flip; b[k] ^= flip; }

    st_v8(outr + off, a);
    st_v8(outi + off, b);
}

extern "C" void kernel_launch(void* const* d_in, const int* in_sizes, int n_in,
                              void* d_out, int out_size)
{
    const float* xr = (const float*)d_in[0];
    const float* xi = (const float*)d_in[1];
    float* out  = (float*)d_out;
    float* outr = out;
    float* outi = out + (size_t)N_ROWS * B_COLS;

    const int blocks = TOTAL8 / THREADS; // 16384, exact
    z_phase_kernel<<<blocks, THREADS>>>(xr, xi, outr, outi);
}